// round 8
// baseline (speedup 1.0000x reference)
#include <cuda_runtime.h>
#include <cstdint>

// SpatialEncoding: dense 8192x8192 scatter, last-write-wins over 8M edges.
//
// R8: fine binning (4096 buckets x 2 rows) with SHALLOW staging (STAGE_CAP 3,
// 112KB smem -> 2 CTAs/SM) so staging (smem-atomic bound) of one CTA overlaps
// the flush (store bound) of its SM-sibling. ~11% of edges overflow to a
// direct global append (bounded, absorbed). P2 identical to R6 (at its
// smem-atomic floor, 59us).
//
// Record (8B): hi = ((s&1)<<13) | d ; lo = ((e+1)<<3) | bias_idx
// Max lo per (row,col) == last write wins (keys unique, order-independent).

#define N_NODES    8192
#define BUCKETS    4096          // 2 src-rows per bucket
#define STAGE_CAP  3             // lambda=2 per (bucket,CTA); ~11% overflow -> global
#define CAP_G      2944          // per-bucket slab (mean 1953, sigma 44 -> +22 sigma)
#define WAVE       8192          // edges per CTA in pass 1
#define P1_THREADS 1024
#define P2_THREADS 512

static __device__ unsigned long long g_bin[(size_t)BUCKETS * CAP_G];  // 96MB
static __device__ int                g_cur[BUCKETS * 8];              // 32B-padded, zero-init

__device__ __forceinline__ void stage_edge(long e, int s, int d, int pl,
                                           unsigned long long* s_stage,
                                           int* s_cnt) {
    int idx = min(max(pl, 1), 5) - 1;                          // 0..4
    unsigned int key = (((unsigned int)e + 1u) << 3) | (unsigned int)idx;
    unsigned long long rec =
        ((unsigned long long)(unsigned int)(((s & 1) << 13) | d) << 32) |
        (unsigned long long)key;
    int bk  = s >> 1;
    int pos = atomicAdd(&s_cnt[bk], 1);
    if (pos < STAGE_CAP) {
        s_stage[bk * STAGE_CAP + pos] = rec;
    } else {
        int gp = atomicAdd(&g_cur[bk * 8], 1);                 // ~11% overflow
        if (gp < CAP_G)
            g_bin[(size_t)bk * CAP_G + gp] = rec;
    }
}

// ---------------- Pass 1: shallow stage + packed flush, 2 CTAs/SM ----------
__global__ void __launch_bounds__(P1_THREADS, 2)
bin_kernel(const int* __restrict__ src,
           const int* __restrict__ dst,
           const int* __restrict__ plen,
           long E) {
    extern __shared__ char smem[];
    unsigned long long* s_stage = (unsigned long long*)smem;           // 4096*3*8 = 96KB
    int* s_cnt = (int*)(smem + (size_t)BUCKETS * STAGE_CAP * 8);       // 16KB

    const int t = threadIdx.x;
    #pragma unroll
    for (int i = 0; i < BUCKETS / P1_THREADS; i++)
        s_cnt[t + i * P1_THREADS] = 0;
    __syncthreads();

    const long base = (long)blockIdx.x * WAVE;
    #pragma unroll
    for (int c = 0; c < WAVE / (P1_THREADS * 4); c++) {
        long e0 = base + (long)c * (P1_THREADS * 4) + (long)t * 4;
        if (e0 + 3 < E) {
            int4 s4 = *reinterpret_cast<const int4*>(&src[e0]);
            int4 d4 = *reinterpret_cast<const int4*>(&dst[e0]);
            int4 p4 = *reinterpret_cast<const int4*>(&plen[e0]);
            stage_edge(e0 + 0, s4.x, d4.x, p4.x, s_stage, s_cnt);
            stage_edge(e0 + 1, s4.y, d4.y, p4.y, s_stage, s_cnt);
            stage_edge(e0 + 2, s4.z, d4.z, p4.z, s_stage, s_cnt);
            stage_edge(e0 + 3, s4.w, d4.w, p4.w, s_stage, s_cnt);
        } else {
            for (long e = e0; e < E && e < e0 + 4; e++)
                stage_edge(e, src[e], dst[e], plen[e], s_stage, s_cnt);
        }
    }
    __syncthreads();

    // packed flush: each thread owns BUCKETS/P1_THREADS buckets
    #pragma unroll
    for (int i = 0; i < BUCKETS / P1_THREADS; i++) {
        int bk = t + i * P1_THREADS;
        int k = min(s_cnt[bk], STAGE_CAP);
        if (k > 0) {
            int gp = atomicAdd(&g_cur[bk * 8], k);
            unsigned long long* dp = &g_bin[(size_t)bk * CAP_G + gp];
            const unsigned long long* sp = &s_stage[bk * STAGE_CAP];
            if (gp + STAGE_CAP <= CAP_G) {          // fast path: unguarded
                #pragma unroll
                for (int j = 0; j < STAGE_CAP; j++)
                    if (j < k) dp[j] = sp[j];
            } else {
                for (int j = 0; j < k; j++)
                    if (gp + j < CAP_G) dp[j] = sp[j];
            }
        }
    }
}

// ---------------- Pass 2: per-bucket resolve + convert (proven R6) --------
__global__ void __launch_bounds__(P2_THREADS, 3)
resolve_kernel(const float* __restrict__ b,
               float* __restrict__ out) {
    extern __shared__ char smem[];
    unsigned int* s_key = (unsigned int*)smem;          // 2*8192*4 = 64KB
    __shared__ float s_b[8];

    const int bk = blockIdx.x;
    const int t  = threadIdx.x;

    // zero 64KB of keys (uint4)
    uint4* kz = (uint4*)s_key;
    #pragma unroll
    for (int i = 0; i < (2 * N_NODES / 4) / P2_THREADS; i++)
        kz[t + i * P2_THREADS] = make_uint4(0u, 0u, 0u, 0u);
    if (t < 8) s_b[t] = (t < 5) ? b[t] : 0.0f;

    int cnt = g_cur[bk * 8];
    if (cnt > CAP_G) cnt = CAP_G;
    __syncthreads();

    // stream records as uint4 (2 records per load); smem atomicMax resolves
    const unsigned long long* __restrict__ recs = &g_bin[(size_t)bk * CAP_G];
    const uint4* __restrict__ recs4 = reinterpret_cast<const uint4*>(recs);
    const int npair = cnt >> 1;
    for (int i = t; i < npair; i += P2_THREADS) {
        uint4 r = recs4[i];
        // record 0: lo=r.x key, hi=r.y addr ; record 1: lo=r.z, hi=r.w
        atomicMax(&s_key[r.y & 0x3FFFu], r.x);
        atomicMax(&s_key[r.w & 0x3FFFu], r.z);
    }
    if (t == 0 && (cnt & 1)) {
        unsigned long long r = recs[cnt - 1];
        atomicMax(&s_key[(unsigned int)(r >> 32) & 0x3FFFu], (unsigned int)r);
    }
    __syncthreads();

    // convert + contiguous 64KB output write (rows bk*2, bk*2+1)
    float* __restrict__ ob = out + (size_t)bk * 2 * N_NODES;
    #pragma unroll
    for (int i = 0; i < (2 * N_NODES / 4) / P2_THREADS; i++) {
        int j4 = t + i * P2_THREADS;
        uint4 k = kz[j4];
        float4 o;
        o.x = k.x ? s_b[k.x & 7u] : 0.0f;
        o.y = k.y ? s_b[k.y & 7u] : 0.0f;
        o.z = k.z ? s_b[k.z & 7u] : 0.0f;
        o.w = k.w ? s_b[k.w & 7u] : 0.0f;
        *reinterpret_cast<float4*>(&ob[j4 * 4]) = o;
    }

    // reset our cursor for the next graph replay (deterministic counts)
    if (t == 0) g_cur[bk * 8] = 0;
}

extern "C" void kernel_launch(void* const* d_in, const int* in_sizes, int n_in,
                              void* d_out, int out_size) {
    // metadata order: x [N,128] f32, src [E] i32, dst [E] i32,
    //                 path_len [E] i32, b [5] f32
    const int*   src  = (const int*)d_in[1];
    const int*   dst  = (const int*)d_in[2];
    const int*   plen = (const int*)d_in[3];
    const float* b    = (const float*)d_in[4];
    float*       out  = (float*)d_out;

    const long E = (long)in_sizes[1];   // 8,000,000

    const size_t p1_smem = (size_t)BUCKETS * STAGE_CAP * 8 + BUCKETS * 4;  // 112KB
    const size_t p2_smem = (size_t)2 * N_NODES * 4;                        // 64KB

    static bool attr_set = false;
    if (!attr_set) {
        cudaFuncSetAttribute(bin_kernel,
                             cudaFuncAttributeMaxDynamicSharedMemorySize, (int)p1_smem);
        cudaFuncSetAttribute(resolve_kernel,
                             cudaFuncAttributeMaxDynamicSharedMemorySize, (int)p2_smem);
        attr_set = true;
    }

    {
        const int blocks = (int)((E + WAVE - 1) / WAVE);   // 977
        bin_kernel<<<blocks, P1_THREADS, p1_smem>>>(src, dst, plen, E);
    }
    {
        resolve_kernel<<<BUCKETS, P2_THREADS, p2_smem>>>(b, out);
    }
}